// round 9
// baseline (speedup 1.0000x reference)
#include <cuda_runtime.h>
#include <cuda_bf16.h>
#include <mma.h>
#include <math.h>
#include <stdint.h>

using namespace nvcuda;

#define BATCH 1024
#define SEQ   200
#define NLIN  400
#define HID   128
#define H2    256
#define H3    384
#define TB    16
#define BL    (BATCH * SEQ)

// ---------------- scratch (static device globals; no allocation) ----------------
__device__ float g_code[(size_t)BATCH * NLIN];
__device__ __nv_bfloat16 g_ah[(size_t)BL * H2];
__device__ __nv_bfloat16 g_al[(size_t)BL * H2];
__device__ float g_xg1 [(size_t)2 * BL * H3];
__device__ float g_h1  [(size_t)BL * H2];

__device__ __forceinline__ float sigf(float x) {
    return 1.f / (1.f + __expf(-x));
}
__device__ __forceinline__ float tanhfast(float x) {
    float e = __expf(-2.f * fabsf(x));
    float t = (1.f - e) / (1.f + e);
    return x < 0.f ? -t : t;
}

#define BAR_SYNC(id)   asm volatile("bar.sync %0, 512;"   :: "r"(id) : "memory")
#define BAR_ARRIVE(id) asm volatile("bar.arrive %0, 512;" :: "r"(id) : "memory")
#define MEMBAR_CTA()   asm volatile("membar.cta;" ::: "memory")

// ---------------- small SGEMM for dec_linear ----------------
__global__ __launch_bounds__(256) void sgemm_nt(
    const float* __restrict__ A, const float* __restrict__ B,
    const float* __restrict__ bias, float* __restrict__ C,
    int M, int N, int K)
{
    __shared__ float As[16][65];
    __shared__ float Bs[16][65];
    int tid = threadIdx.x;
    int tx = tid & 15, ty = tid >> 4;
    int bm0 = blockIdx.x * 64, bn0 = blockIdx.y * 64;
    int lrow = tid >> 2;
    int lc4  = (tid & 3) * 4;

    float acc[4][4] = {};

    for (int k0 = 0; k0 < K; k0 += 16) {
        float4 av = *(const float4*)(A + (size_t)(bm0 + lrow) * K + k0 + lc4);
        float4 bv = make_float4(0.f, 0.f, 0.f, 0.f);
        if (bn0 + lrow < N)
            bv = *(const float4*)(B + (size_t)(bn0 + lrow) * K + k0 + lc4);
        As[lc4 + 0][lrow] = av.x; As[lc4 + 1][lrow] = av.y;
        As[lc4 + 2][lrow] = av.z; As[lc4 + 3][lrow] = av.w;
        Bs[lc4 + 0][lrow] = bv.x; Bs[lc4 + 1][lrow] = bv.y;
        Bs[lc4 + 2][lrow] = bv.z; Bs[lc4 + 3][lrow] = bv.w;
        __syncthreads();
        #pragma unroll
        for (int kk = 0; kk < 16; ++kk) {
            float a[4], b[4];
            #pragma unroll
            for (int i = 0; i < 4; ++i) { a[i] = As[kk][ty * 4 + i]; b[i] = Bs[kk][tx * 4 + i]; }
            #pragma unroll
            for (int i = 0; i < 4; ++i)
                #pragma unroll
                for (int j = 0; j < 4; ++j)
                    acc[i][j] = fmaf(a[i], b[j], acc[i][j]);
        }
        __syncthreads();
    }

    #pragma unroll
    for (int i = 0; i < 4; ++i) {
        int row = bm0 + ty * 4 + i;
        #pragma unroll
        for (int j = 0; j < 4; ++j) {
            int col = bn0 + tx * 4 + j;
            if (col < N)
                C[(size_t)row * N + col] = acc[i][j] + bias[col];
        }
    }
}

// ---------------- layer-1 projection GEMM v2 (wmma bf16, 3-term hi/lo) ----------------
// Now also folds bhh into the bias for the r/z gate columns (cols < 256).
#define LDW2 264
#define LDA2 40
#define LDE2 132
#define X2_BIAS 0
#define X2_WH   512
#define X2_WL   (X2_WH + 128 * LDW2 * 2)
#define X2_AH   (X2_WL + 128 * LDW2 * 2)
#define X2_AL   (X2_AH + 128 * LDA2 * 2)
#define X2_EPI  (X2_AL + 128 * LDA2 * 2)
#define SMEM_X2 (X2_EPI + 128 * LDE2 * 4)

__global__ __launch_bounds__(256, 1) void xgemm2(
    const __nv_bfloat16* __restrict__ Ah, const __nv_bfloat16* __restrict__ Al,
    const float* __restrict__ Bf, const float* __restrict__ Bb,
    const float* __restrict__ biasf, const float* __restrict__ biasb,
    const float* __restrict__ bhhf, const float* __restrict__ bhhb,
    float* __restrict__ C)
{
    extern __shared__ char smem[];
    float* sBias = (float*)(smem + X2_BIAS);
    __nv_bfloat16* sWh = (__nv_bfloat16*)(smem + X2_WH);
    __nv_bfloat16* sWl = (__nv_bfloat16*)(smem + X2_WL);
    __nv_bfloat16* sAh = (__nv_bfloat16*)(smem + X2_AH);
    __nv_bfloat16* sAl = (__nv_bfloat16*)(smem + X2_AL);
    float* sEpi = (float*)(smem + X2_EPI);

    const int tid = threadIdx.x;
    const int wid = tid >> 5;
    const int wm = wid & 3;
    const int wn = wid >> 2;

    const int bx = blockIdx.x;
    const int dir = bx / 3;
    const int ncol0 = (bx % 3) * 128;
    const float* W = dir ? Bb : Bf;
    const float* bias = dir ? biasb : biasf;
    const float* bhh = dir ? bhhb : bhhf;
    float* Cb = C + (size_t)dir * BL * H3;

    for (int idx = tid; idx < 128 * 256; idx += 256) {
        int n = idx >> 8, k = idx & 255;
        float w = W[(size_t)(ncol0 + n) * H2 + k];
        __nv_bfloat16 hi = __float2bfloat16(w);
        __nv_bfloat16 lo = __float2bfloat16(w - __bfloat162float(hi));
        sWh[n * LDW2 + k] = hi;
        sWl[n * LDW2 + k] = lo;
    }
    if (tid < 128) {
        int c = ncol0 + tid;
        float bv = bias[c];
        if (c < 256) bv += bhh[c];   // fold bhh for r,z gates (n-gate bhh stays inside r-multiply)
        sBias[tid] = bv;
    }

    const int pr = tid >> 1;
    const int cbase = (tid & 1) * 16;

    wmma::fragment<wmma::accumulator, 16, 16, 16, float> acc[2][4];
    #pragma unroll
    for (int i = 0; i < 2; ++i)
        #pragma unroll
        for (int j = 0; j < 4; ++j)
            wmma::fill_fragment(acc[i][j], 0.f);

    uint4 ph0, ph1, pl0, pl1;
    {
        size_t g = (size_t)blockIdx.y * 128 * H2 + (size_t)pr * H2 + cbase;
        ph0 = *(const uint4*)(Ah + g);     ph1 = *(const uint4*)(Ah + g + 8);
        pl0 = *(const uint4*)(Al + g);     pl1 = *(const uint4*)(Al + g + 8);
    }

    for (int it = 0; it < 8; ++it) {
        const size_t m0 = ((size_t)it * 200 + blockIdx.y) * 128;

        for (int c = 0; c < 8; ++c) {
            __syncthreads();
            *(uint4*)&sAh[pr * LDA2 + cbase]     = ph0;
            *(uint4*)&sAh[pr * LDA2 + cbase + 8] = ph1;
            *(uint4*)&sAl[pr * LDA2 + cbase]     = pl0;
            *(uint4*)&sAl[pr * LDA2 + cbase + 8] = pl1;

            if (c < 7 || it < 7) {
                int nc = (c < 7) ? c + 1 : 0;
                size_t nm0 = (c < 7) ? m0 : ((size_t)(it + 1) * 200 + blockIdx.y) * 128;
                size_t g = (nm0 + pr) * H2 + nc * 32 + cbase;
                ph0 = *(const uint4*)(Ah + g);     ph1 = *(const uint4*)(Ah + g + 8);
                pl0 = *(const uint4*)(Al + g);     pl1 = *(const uint4*)(Al + g + 8);
            }
            __syncthreads();

            #pragma unroll
            for (int kk = 0; kk < 2; ++kk) {
                wmma::fragment<wmma::matrix_a, 16, 16, 16, __nv_bfloat16, wmma::row_major> fah[2], fal[2];
                wmma::fragment<wmma::matrix_b, 16, 16, 16, __nv_bfloat16, wmma::col_major> fbh[4], fbl[4];
                #pragma unroll
                for (int i = 0; i < 2; ++i) {
                    wmma::load_matrix_sync(fah[i], sAh + (wm * 32 + i * 16) * LDA2 + kk * 16, LDA2);
                    wmma::load_matrix_sync(fal[i], sAl + (wm * 32 + i * 16) * LDA2 + kk * 16, LDA2);
                }
                #pragma unroll
                for (int j = 0; j < 4; ++j) {
                    wmma::load_matrix_sync(fbh[j], sWh + (wn * 64 + j * 16) * LDW2 + c * 32 + kk * 16, LDW2);
                    wmma::load_matrix_sync(fbl[j], sWl + (wn * 64 + j * 16) * LDW2 + c * 32 + kk * 16, LDW2);
                }
                #pragma unroll
                for (int i = 0; i < 2; ++i)
                    #pragma unroll
                    for (int j = 0; j < 4; ++j) {
                        wmma::mma_sync(acc[i][j], fah[i], fbh[j], acc[i][j]);
                        wmma::mma_sync(acc[i][j], fah[i], fbl[j], acc[i][j]);
                        wmma::mma_sync(acc[i][j], fal[i], fbh[j], acc[i][j]);
                    }
            }
        }

        __syncthreads();
        #pragma unroll
        for (int i = 0; i < 2; ++i)
            #pragma unroll
            for (int j = 0; j < 4; ++j) {
                wmma::store_matrix_sync(sEpi + (wm * 32 + i * 16) * LDE2 + wn * 64 + j * 16,
                                        acc[i][j], LDE2, wmma::mem_row_major);
                wmma::fill_fragment(acc[i][j], 0.f);
            }
        __syncthreads();
        for (int idx = tid; idx < 128 * 32; idx += 256) {
            int r = idx >> 5, c4 = (idx & 31) * 4;
            float4 v = *(float4*)&sEpi[r * LDE2 + c4];
            v.x += sBias[c4 + 0]; v.y += sBias[c4 + 1];
            v.z += sBias[c4 + 2]; v.w += sBias[c4 + 3];
            *(float4*)(Cb + (m0 + r) * H3 + ncol0 + c4) = v;
        }
    }
}

// ---------------- warp-specialized tensor-core GRU layer ----------------
// 512 threads: warps 0-11 = mma producers, warps 12-15 = gate consumers.
// h state in gate-warp registers; smem h (bf16 hi/lo) only feeds a-fragments.
// Pipeline: mma chunk0 -> bar1 -> [gates chunk0 || mma chunk1(regs)] -> bar2 ->
//           store chunk1 -> bar3 -> gates chunk1 + writeback -> bar4 -> next step.
#define LDWP 392
#define LDH  136
#define LDEPI 196
#define G2_WH   0
#define G2_WL   (G2_WH + 128 * LDWP * 2)     // 100352
#define G2_HH   (G2_WL + 128 * LDWP * 2)     // 200704
#define G2_HL   (G2_HH + TB * LDH * 2)       // 205056
#define G2_EPI  (G2_HL + TB * LDH * 2)       // 209408
#define G2_BHN  (G2_EPI + TB * LDEPI * 4)    // 221952
#define G2_BIH  (G2_BHN + HID * 4)           // 222464
#define G2_WIH  (G2_BIH + H3 * 4)            // 224000
#define SMEM_G2 (G2_WIH + H3 * 2 * 4)        // 227072

template <int LAYER>
__global__ __launch_bounds__(512, 1) void gru_tc(
    const float* __restrict__ code,
    const float* __restrict__ xg,
    const float* __restrict__ Wih_f, const float* __restrict__ Wih_b,
    const float* __restrict__ Whh_f, const float* __restrict__ Whh_b,
    const float* __restrict__ bih_f, const float* __restrict__ bih_b,
    const float* __restrict__ bhh_f, const float* __restrict__ bhh_b,
    float* __restrict__ houtF,
    __nv_bfloat16* __restrict__ houtH,
    __nv_bfloat16* __restrict__ houtL)
{
    extern __shared__ char smem[];
    __nv_bfloat16* sWh = (__nv_bfloat16*)(smem + G2_WH);
    __nv_bfloat16* sWl = (__nv_bfloat16*)(smem + G2_WL);
    __nv_bfloat16* sHh = (__nv_bfloat16*)(smem + G2_HH);
    __nv_bfloat16* sHl = (__nv_bfloat16*)(smem + G2_HL);
    float* sEpi  = (float*)(smem + G2_EPI);
    float* sBhhN = (float*)(smem + G2_BHN);
    float* sBih  = (float*)(smem + G2_BIH);
    float* sWih  = (float*)(smem + G2_WIH);

    const int tid = threadIdx.x;
    const int dir = blockIdx.y;
    const int gb0 = blockIdx.x * TB;
    const float* Whh = dir ? Whh_b : Whh_f;
    const float* bhh = dir ? bhh_b : bhh_f;

    // Whh -> permuted bf16 hi/lo: sWh[j][(k>>6)*192 + 3*(k&63) + g]
    for (int idx = tid; idx < H3 * HID; idx += 512) {
        int r = idx >> 7, j = idx & 127;
        int g = r >> 7, k = r & 127;
        int colp = (k >> 6) * 192 + 3 * (k & 63) + g;
        float w = Whh[r * HID + j];
        __nv_bfloat16 hi = __float2bfloat16(w);
        __nv_bfloat16 lo = __float2bfloat16(w - __bfloat162float(hi));
        sWh[j * LDWP + colp] = hi;
        sWl[j * LDWP + colp] = lo;
    }
    for (int idx = tid; idx < HID; idx += 512) sBhhN[idx] = bhh[256 + idx];
    if (LAYER == 0) {
        const float* Wih = dir ? Wih_b : Wih_f;
        const float* bih = dir ? bih_b : bih_f;
        for (int idx = tid; idx < H3; idx += 512) {
            sBih[idx] = bih[idx] + (idx < 256 ? bhh[idx] : 0.f);
            sWih[idx * 2 + 0] = Wih[idx * 2 + 0];
            sWih[idx * 2 + 1] = Wih[idx * 2 + 1];
        }
    }
    for (int idx = tid; idx < TB * LDH; idx += 512) {
        sHh[idx] = __float2bfloat16(0.f);
        sHl[idx] = __float2bfloat16(0.f);
    }
    __syncthreads();

    const int wid = tid >> 5;

    if (wid < 12) {
        // ================= mma producer path =================
        for (int t = 0; t < SEQ; ++t) {
            BAR_SYNC(4);   // h(t-1) published (gates pre-arm before loop)

            wmma::fragment<wmma::matrix_a, 16, 16, 16, __nv_bfloat16, wmma::row_major> aH[8], aL[8];
            #pragma unroll
            for (int jf = 0; jf < 8; ++jf) {
                wmma::load_matrix_sync(aH[jf], sHh + jf * 16, LDH);
                wmma::load_matrix_sync(aL[jf], sHl + jf * 16, LDH);
            }

            // chunk 0 (cols' 0..191)
            {
                wmma::fragment<wmma::accumulator, 16, 16, 16, float> acc;
                wmma::fill_fragment(acc, 0.f);
                #pragma unroll
                for (int jf = 0; jf < 8; ++jf) {
                    wmma::fragment<wmma::matrix_b, 16, 16, 16, __nv_bfloat16, wmma::row_major> bH, bL;
                    wmma::load_matrix_sync(bH, sWh + (jf * 16) * LDWP + wid * 16, LDWP);
                    wmma::load_matrix_sync(bL, sWl + (jf * 16) * LDWP + wid * 16, LDWP);
                    wmma::mma_sync(acc, aH[jf], bH, acc);
                    wmma::mma_sync(acc, aH[jf], bL, acc);
                    wmma::mma_sync(acc, aL[jf], bH, acc);
                }
                wmma::store_matrix_sync(sEpi + wid * 16, acc, LDEPI, wmma::mem_row_major);
            }
            MEMBAR_CTA();
            BAR_ARRIVE(1);   // epi chunk0 ready

            // chunk 1 (cols' 192..383) into registers while gates consume chunk0
            {
                wmma::fragment<wmma::accumulator, 16, 16, 16, float> acc;
                wmma::fill_fragment(acc, 0.f);
                #pragma unroll
                for (int jf = 0; jf < 8; ++jf) {
                    wmma::fragment<wmma::matrix_b, 16, 16, 16, __nv_bfloat16, wmma::row_major> bH, bL;
                    wmma::load_matrix_sync(bH, sWh + (jf * 16) * LDWP + 192 + wid * 16, LDWP);
                    wmma::load_matrix_sync(bL, sWl + (jf * 16) * LDWP + 192 + wid * 16, LDWP);
                    wmma::mma_sync(acc, aH[jf], bH, acc);
                    wmma::mma_sync(acc, aH[jf], bL, acc);
                    wmma::mma_sync(acc, aL[jf], bH, acc);
                }
                BAR_SYNC(2);  // gates done reading chunk0
                wmma::store_matrix_sync(sEpi + wid * 16, acc, LDEPI, wmma::mem_row_major);
            }
            MEMBAR_CTA();
            BAR_ARRIVE(3);   // epi chunk1 ready
        }
    } else {
        // ================= gate consumer path =================
        const int g = tid - 384;          // 0..127
        const int b = g >> 3;             // batch row
        const int kb = (g & 7) * 8;       // k base (0..56)
        float h[16];
        #pragma unroll
        for (int i = 0; i < 16; ++i) h[i] = 0.f;

        BAR_ARRIVE(4);   // prime: h(−1)=0 already in smem

        for (int t = 0; t < SEQ; ++t) {
            const int tt = dir ? (SEQ - 1 - t) : t;

            // ---- x-gate prefetch (overlaps mma chunk0) ----
            float xr[16], xz[16], xn[16];
            if (LAYER == 1) {
                const float* xp = xg + ((size_t)dir * BL + (size_t)(gb0 + b) * SEQ + tt) * H3;
                #pragma unroll
                for (int q = 0; q < 2; ++q) {
                    float4 v;
                    v = *(const float4*)(xp + q * 64 + kb);           xr[q*8+0]=v.x; xr[q*8+1]=v.y; xr[q*8+2]=v.z; xr[q*8+3]=v.w;
                    v = *(const float4*)(xp + q * 64 + kb + 4);       xr[q*8+4]=v.x; xr[q*8+5]=v.y; xr[q*8+6]=v.z; xr[q*8+7]=v.w;
                    v = *(const float4*)(xp + 128 + q * 64 + kb);     xz[q*8+0]=v.x; xz[q*8+1]=v.y; xz[q*8+2]=v.z; xz[q*8+3]=v.w;
                    v = *(const float4*)(xp + 128 + q * 64 + kb + 4); xz[q*8+4]=v.x; xz[q*8+5]=v.y; xz[q*8+6]=v.z; xz[q*8+7]=v.w;
                    v = *(const float4*)(xp + 256 + q * 64 + kb);     xn[q*8+0]=v.x; xn[q*8+1]=v.y; xn[q*8+2]=v.z; xn[q*8+3]=v.w;
                    v = *(const float4*)(xp + 256 + q * 64 + kb + 4); xn[q*8+4]=v.x; xn[q*8+5]=v.y; xn[q*8+6]=v.z; xn[q*8+7]=v.w;
                }
            } else {
                float c0 = __ldg(&code[(size_t)(gb0 + b) * NLIN + tt * 2 + 0]);
                float c1 = __ldg(&code[(size_t)(gb0 + b) * NLIN + tt * 2 + 1]);
                #pragma unroll
                for (int i = 0; i < 16; ++i) {
                    int k = (i >> 3) * 64 + kb + (i & 7);
                    xr[i] = fmaf(c0, sWih[k * 2],         fmaf(c1, sWih[k * 2 + 1],         sBih[k]));
                    xz[i] = fmaf(c0, sWih[(128 + k) * 2], fmaf(c1, sWih[(128 + k) * 2 + 1], sBih[128 + k]));
                    xn[i] = fmaf(c0, sWih[(256 + k) * 2], fmaf(c1, sWih[(256 + k) * 2 + 1], sBih[256 + k]));
                }
            }

            // ---- gates chunk 0 (k = kb..kb+7) ----
            BAR_SYNC(1);
            #pragma unroll
            for (int i = 0; i < 8; ++i) {
                int k = kb + i;
                const float* e = sEpi + b * LDEPI + 3 * k;
                float r = sigf(xr[i] + e[0]);
                float z = sigf(xz[i] + e[1]);
                float n = tanhfast(xn[i] + r * (e[2] + sBhhN[k]));
                h[i] = (1.f - z) * n + z * h[i];
            }
            BAR_ARRIVE(2);   // chunk0 epi consumed

            // ---- gates chunk 1 (k = 64+kb..64+kb+7) ----
            BAR_SYNC(3);
            #pragma unroll
            for (int i = 0; i < 8; ++i) {
                int kl = kb + i;
                int k = 64 + kl;
                const float* e = sEpi + b * LDEPI + 3 * kl;
                float r = sigf(xr[8 + i] + e[0]);
                float z = sigf(xz[8 + i] + e[1]);
                float n = tanhfast(xn[8 + i] + r * (e[2] + sBhhN[k]));
                h[8 + i] = (1.f - z) * n + z * h[8 + i];
            }

            // ---- writeback: smem h (bf16 hi/lo) + global ----
            const size_t orow = ((size_t)(gb0 + b) * SEQ + tt) * H2 + dir * HID;
            __nv_bfloat16 hiA[8], loA[8], hiB[8], loB[8];
            #pragma unroll
            for (int i = 0; i < 8; ++i) {
                float v = h[i];
                hiA[i] = __float2bfloat16(v);
                loA[i] = __float2bfloat16(v - __bfloat162float(hiA[i]));
                float w = h[8 + i];
                hiB[i] = __float2bfloat16(w);
                loB[i] = __float2bfloat16(w - __bfloat162float(hiB[i]));
            }
            *(uint4*)&sHh[b * LDH + kb]      = *(uint4*)hiA;
            *(uint4*)&sHl[b * LDH + kb]      = *(uint4*)loA;
            *(uint4*)&sHh[b * LDH + 64 + kb] = *(uint4*)hiB;
            *(uint4*)&sHl[b * LDH + 64 + kb] = *(uint4*)loB;
            if (LAYER == 0) {
                *(uint4*)&houtH[orow + kb]      = *(uint4*)hiA;
                *(uint4*)&houtL[orow + kb]      = *(uint4*)loA;
                *(uint4*)&houtH[orow + 64 + kb] = *(uint4*)hiB;
                *(uint4*)&houtL[orow + 64 + kb] = *(uint4*)loB;
            } else {
                *(float4*)&houtF[orow + kb]          = *(float4*)&h[0];
                *(float4*)&houtF[orow + kb + 4]      = *(float4*)&h[4];
                *(float4*)&houtF[orow + 64 + kb]     = *(float4*)&h[8];
                *(float4*)&houtF[orow + 64 + kb + 4] = *(float4*)&h[12];
            }
            MEMBAR_CTA();
            BAR_ARRIVE(4);   // new h published
        }
    }
}

// ---------------- final head ----------------
__global__ __launch_bounds__(256) void final_kernel(
    const float* __restrict__ h1, const float* __restrict__ Wf,
    const float* __restrict__ bf, float* __restrict__ out)
{
    __shared__ float sW[H2];
    int tid = threadIdx.x;
    sW[tid] = Wf[tid];
    __syncthreads();
    int w = tid >> 5, l = tid & 31;
    size_t row = (size_t)blockIdx.x * 8 + w;
    const float* hr = h1 + row * H2;
    float s = 0.f;
    #pragma unroll
    for (int i = 0; i < 8; ++i)
        s = fmaf(hr[l + i * 32], sW[l + i * 32], s);
    #pragma unroll
    for (int off = 16; off; off >>= 1)
        s += __shfl_xor_sync(0xffffffffu, s, off);
    if (l == 0)
        out[row] = 1.f / (1.f + __expf(-(s + bf[0])));
}

// ---------------- launch ----------------
extern "C" void kernel_launch(void* const* d_in, const int* in_sizes, int n_in,
                              void* d_out, int out_size)
{
    const float* received = (const float*)d_in[0];
    const float* W_lin    = (const float*)d_in[1];
    const float* b_lin    = (const float*)d_in[2];
    const float* Wih0f = (const float*)d_in[3],  *Whh0f = (const float*)d_in[4];
    const float* bih0f = (const float*)d_in[5],  *bhh0f = (const float*)d_in[6];
    const float* Wih0b = (const float*)d_in[7],  *Whh0b = (const float*)d_in[8];
    const float* bih0b = (const float*)d_in[9],  *bhh0b = (const float*)d_in[10];
    const float* Wih1f = (const float*)d_in[11], *Whh1f = (const float*)d_in[12];
    const float* bih1f = (const float*)d_in[13], *bhh1f = (const float*)d_in[14];
    const float* Wih1b = (const float*)d_in[15], *Whh1b = (const float*)d_in[16];
    const float* bih1b = (const float*)d_in[17], *bhh1b = (const float*)d_in[18];
    const float* Wf    = (const float*)d_in[19], *bf    = (const float*)d_in[20];
    float* out = (float*)d_out;

    float *code, *xg1, *h1;
    __nv_bfloat16 *ah, *al;
    cudaGetSymbolAddress((void**)&code, g_code);
    cudaGetSymbolAddress((void**)&ah,   g_ah);
    cudaGetSymbolAddress((void**)&al,   g_al);
    cudaGetSymbolAddress((void**)&xg1,  g_xg1);
    cudaGetSymbolAddress((void**)&h1,   g_h1);

    cudaFuncSetAttribute(gru_tc<0>, cudaFuncAttributeMaxDynamicSharedMemorySize, (int)SMEM_G2);
    cudaFuncSetAttribute(gru_tc<1>, cudaFuncAttributeMaxDynamicSharedMemorySize, (int)SMEM_G2);
    cudaFuncSetAttribute(xgemm2, cudaFuncAttributeMaxDynamicSharedMemorySize, (int)SMEM_X2);

    // 1) dec_linear
    sgemm_nt<<<dim3(BATCH / 64, (NLIN + 63) / 64), 256>>>(
        received, W_lin, b_lin, code, BATCH, NLIN, NLIN);

    // 2) layer-0 bidirectional GRU (warp-specialized TC recurrence) -> bf16 hi/lo h0
    gru_tc<0><<<dim3(BATCH / TB, 2), 512, SMEM_G2>>>(
        code, nullptr, Wih0f, Wih0b, Whh0f, Whh0b, bih0f, bih0b, bhh0f, bhh0b,
        nullptr, ah, al);

    // 3) layer-1 input projections (wmma bf16 v2, bhh folded for r/z)
    xgemm2<<<dim3(6, 200), 256, SMEM_X2>>>(
        ah, al, Wih1f, Wih1b, bih1f, bih1b, bhh1f, bhh1b, xg1);

    // 4) layer-1 bidirectional GRU (warp-specialized TC recurrence)
    gru_tc<1><<<dim3(BATCH / TB, 2), 512, SMEM_G2>>>(
        nullptr, xg1, nullptr, nullptr, Whh1f, Whh1b, bih1f, bih1b, bhh1f, bhh1b,
        h1, nullptr, nullptr);

    // 5) output head
    final_kernel<<<BL / 8, 256>>>(h1, Wf, bf, out);
}

// round 10
// speedup vs baseline: 1.2980x; 1.2980x over previous
#include <cuda_runtime.h>
#include <cuda_bf16.h>
#include <mma.h>
#include <math.h>
#include <stdint.h>

using namespace nvcuda;

#define BATCH 1024
#define SEQ   200
#define NLIN  400
#define HID   128
#define H2    256
#define H3    384
#define TB    16
#define BL    (BATCH * SEQ)

// ---------------- scratch (static device globals; no allocation) ----------------
__device__ float g_code[(size_t)BATCH * NLIN];
__device__ __nv_bfloat16 g_ah[(size_t)BL * H2];
__device__ __nv_bfloat16 g_al[(size_t)BL * H2];
__device__ float g_xg1 [(size_t)2 * BL * H3];
__device__ float g_h1  [(size_t)BL * H2];

__device__ __forceinline__ float sigf(float x) {
    return 1.f / (1.f + __expf(-x));
}
__device__ __forceinline__ float tanhfast(float x) {
    float e = __expf(-2.f * fabsf(x));
    float t = (1.f - e) / (1.f + e);
    return x < 0.f ? -t : t;
}

// ---------------- small SGEMM for dec_linear ----------------
__global__ __launch_bounds__(256) void sgemm_nt(
    const float* __restrict__ A, const float* __restrict__ B,
    const float* __restrict__ bias, float* __restrict__ C,
    int M, int N, int K)
{
    __shared__ float As[16][65];
    __shared__ float Bs[16][65];
    int tid = threadIdx.x;
    int tx = tid & 15, ty = tid >> 4;
    int bm0 = blockIdx.x * 64, bn0 = blockIdx.y * 64;
    int lrow = tid >> 2;
    int lc4  = (tid & 3) * 4;

    float acc[4][4] = {};

    for (int k0 = 0; k0 < K; k0 += 16) {
        float4 av = *(const float4*)(A + (size_t)(bm0 + lrow) * K + k0 + lc4);
        float4 bv = make_float4(0.f, 0.f, 0.f, 0.f);
        if (bn0 + lrow < N)
            bv = *(const float4*)(B + (size_t)(bn0 + lrow) * K + k0 + lc4);
        As[lc4 + 0][lrow] = av.x; As[lc4 + 1][lrow] = av.y;
        As[lc4 + 2][lrow] = av.z; As[lc4 + 3][lrow] = av.w;
        Bs[lc4 + 0][lrow] = bv.x; Bs[lc4 + 1][lrow] = bv.y;
        Bs[lc4 + 2][lrow] = bv.z; Bs[lc4 + 3][lrow] = bv.w;
        __syncthreads();
        #pragma unroll
        for (int kk = 0; kk < 16; ++kk) {
            float a[4], b[4];
            #pragma unroll
            for (int i = 0; i < 4; ++i) { a[i] = As[kk][ty * 4 + i]; b[i] = Bs[kk][tx * 4 + i]; }
            #pragma unroll
            for (int i = 0; i < 4; ++i)
                #pragma unroll
                for (int j = 0; j < 4; ++j)
                    acc[i][j] = fmaf(a[i], b[j], acc[i][j]);
        }
        __syncthreads();
    }

    #pragma unroll
    for (int i = 0; i < 4; ++i) {
        int row = bm0 + ty * 4 + i;
        #pragma unroll
        for (int j = 0; j < 4; ++j) {
            int col = bn0 + tx * 4 + j;
            if (col < N)
                C[(size_t)row * N + col] = acc[i][j] + bias[col];
        }
    }
}

// ---------------- layer-1 projection GEMM v3 ----------------
// C[2][BL][384] = h0[BL][256] @ Wih1{f,b}[384][256]^T + bias (3-term bf16 hi/lo).
// grid (6, 200). 256 threads = 8 warps (4M x 2N), warp tile 32x64, CTA tile 128x128.
// K-chunks of 64, double-buffered A (1 sync/chunk). Bias pre-loaded into accumulator
// fragments; results stored DIRECTLY to global (no smem epilogue).
#define LDW3 264
#define LDA3 72
#define LDB3 132
#define X3_BIAS 0
#define X3_WH   8448
#define X3_WL   (X3_WH  + 128 * LDW3 * 2)
#define X3_AH0  (X3_WL  + 128 * LDW3 * 2)
#define X3_AH1  (X3_AH0 + 128 * LDA3 * 2)
#define X3_AL0  (X3_AH1 + 128 * LDA3 * 2)
#define X3_AL1  (X3_AL0 + 128 * LDA3 * 2)
#define SMEM_X3 (X3_AL1 + 128 * LDA3 * 2)     // 217344 bytes

__global__ __launch_bounds__(256, 1) void xgemm3(
    const __nv_bfloat16* __restrict__ Ah, const __nv_bfloat16* __restrict__ Al,
    const float* __restrict__ Bf, const float* __restrict__ Bb,
    const float* __restrict__ biasf, const float* __restrict__ biasb,
    float* __restrict__ C)
{
    extern __shared__ char smem[];
    float* sBias = (float*)(smem + X3_BIAS);                       // [16][LDB3]
    __nv_bfloat16* sWh = (__nv_bfloat16*)(smem + X3_WH);           // [128][LDW3]
    __nv_bfloat16* sWl = (__nv_bfloat16*)(smem + X3_WL);
    __nv_bfloat16* sAh[2] = { (__nv_bfloat16*)(smem + X3_AH0), (__nv_bfloat16*)(smem + X3_AH1) };
    __nv_bfloat16* sAl[2] = { (__nv_bfloat16*)(smem + X3_AL0), (__nv_bfloat16*)(smem + X3_AL1) };

    const int tid = threadIdx.x;
    const int wid = tid >> 5;
    const int wm = wid & 3;          // rows wm*32
    const int wn = wid >> 2;         // cols wn*64

    const int bx = blockIdx.x;
    const int dir = bx / 3;
    const int ncol0 = (bx % 3) * 128;
    const float* W = dir ? Bb : Bf;
    const float* bias = dir ? biasb : biasf;
    float* Cb = C + (size_t)dir * BL * H3;

    // W tile (128 out-cols x 256 k) -> bf16 hi/lo, once per CTA
    for (int idx = tid; idx < 128 * 256; idx += 256) {
        int n = idx >> 8, k = idx & 255;
        float w = W[(size_t)(ncol0 + n) * H2 + k];
        __nv_bfloat16 hi = __float2bfloat16(w);
        __nv_bfloat16 lo = __float2bfloat16(w - __bfloat162float(hi));
        sWh[n * LDW3 + k] = hi;
        sWl[n * LDW3 + k] = lo;
    }
    // bias broadcast tile: every row = bias vector
    for (int idx = tid; idx < 16 * 128; idx += 256) {
        int r = idx >> 7, c = idx & 127;
        sBias[r * LDB3 + c] = bias[ncol0 + c];
    }

    // A prefetch mapping: row pr (0..127), 32 bf16 from col pc
    const int pr = tid >> 1;
    const int pc = (tid & 1) * 32;
    uint4 ph[4], pl[4];

    // fetch global chunk g (0..31): it = g>>2, c = g&3
    #define FETCH_CHUNK(g) do { \
        int _it = (g) >> 2, _c = (g) & 3; \
        size_t _base = (((size_t)_it * 200 + blockIdx.y) * 128 + pr) * H2 + _c * 64 + pc; \
        ph[0] = *(const uint4*)(Ah + _base);      ph[1] = *(const uint4*)(Ah + _base + 8); \
        ph[2] = *(const uint4*)(Ah + _base + 16); ph[3] = *(const uint4*)(Ah + _base + 24); \
        pl[0] = *(const uint4*)(Al + _base);      pl[1] = *(const uint4*)(Al + _base + 8); \
        pl[2] = *(const uint4*)(Al + _base + 16); pl[3] = *(const uint4*)(Al + _base + 24); \
    } while (0)

    FETCH_CHUNK(0);
    __syncthreads();   // W + bias tiles ready

    for (int it = 0; it < 8; ++it) {
        const size_t m0 = ((size_t)it * 200 + blockIdx.y) * 128;

        // accumulators start at bias (broadcast rows)
        wmma::fragment<wmma::accumulator, 16, 16, 16, float> acc[2][4];
        #pragma unroll
        for (int i = 0; i < 2; ++i)
            #pragma unroll
            for (int j = 0; j < 4; ++j)
                wmma::load_matrix_sync(acc[i][j], sBias + wn * 64 + j * 16, LDB3, wmma::mem_row_major);

        for (int c = 0; c < 4; ++c) {
            const int g = it * 4 + c;
            const int buf = g & 1;

            // store prefetched chunk g; safe: buf last read at chunk g-2,
            // whose mma completed before the sync at chunk g-1.
            __nv_bfloat16* dH = sAh[buf] + pr * LDA3 + pc;
            __nv_bfloat16* dL = sAl[buf] + pr * LDA3 + pc;
            *(uint4*)(dH)      = ph[0]; *(uint4*)(dH + 8)  = ph[1];
            *(uint4*)(dH + 16) = ph[2]; *(uint4*)(dH + 24) = ph[3];
            *(uint4*)(dL)      = pl[0]; *(uint4*)(dL + 8)  = pl[1];
            *(uint4*)(dL + 16) = pl[2]; *(uint4*)(dL + 24) = pl[3];

            if (g + 1 < 32) FETCH_CHUNK(g + 1);
            __syncthreads();   // chunk g visible; all warps past mma g-1

            #pragma unroll
            for (int kk = 0; kk < 4; ++kk) {
                wmma::fragment<wmma::matrix_a, 16, 16, 16, __nv_bfloat16, wmma::row_major> fah[2], fal[2];
                wmma::fragment<wmma::matrix_b, 16, 16, 16, __nv_bfloat16, wmma::col_major> fbh[4], fbl[4];
                #pragma unroll
                for (int i = 0; i < 2; ++i) {
                    wmma::load_matrix_sync(fah[i], sAh[buf] + (wm * 32 + i * 16) * LDA3 + kk * 16, LDA3);
                    wmma::load_matrix_sync(fal[i], sAl[buf] + (wm * 32 + i * 16) * LDA3 + kk * 16, LDA3);
                }
                #pragma unroll
                for (int j = 0; j < 4; ++j) {
                    wmma::load_matrix_sync(fbh[j], sWh + (wn * 64 + j * 16) * LDW3 + c * 64 + kk * 16, LDW3);
                    wmma::load_matrix_sync(fbl[j], sWl + (wn * 64 + j * 16) * LDW3 + c * 64 + kk * 16, LDW3);
                }
                #pragma unroll
                for (int i = 0; i < 2; ++i)
                    #pragma unroll
                    for (int j = 0; j < 4; ++j) {
                        wmma::mma_sync(acc[i][j], fah[i], fbh[j], acc[i][j]);
                        wmma::mma_sync(acc[i][j], fah[i], fbl[j], acc[i][j]);
                        wmma::mma_sync(acc[i][j], fal[i], fbh[j], acc[i][j]);
                    }
            }
        }

        // direct global store (no smem epilogue, no syncs)
        #pragma unroll
        for (int i = 0; i < 2; ++i)
            #pragma unroll
            for (int j = 0; j < 4; ++j)
                wmma::store_matrix_sync(
                    Cb + (m0 + wm * 32 + i * 16) * H3 + ncol0 + wn * 64 + j * 16,
                    acc[i][j], H3, wmma::mem_row_major);
    }
    #undef FETCH_CHUNK
}

// ---------------- tensor-core GRU layer (R8-proven symmetric version) ----------------
#define LDWP 392
#define LDH  136
#define LDEPI 196
#define GOFF_WH  0
#define GOFF_WL  (GOFF_WH + 128 * LDWP * 2)
#define GOFF_HH  (GOFF_WL + 128 * LDWP * 2)
#define GOFF_HL  (GOFF_HH + TB * LDH * 2)
#define GOFF_EPI (GOFF_HL + TB * LDH * 2)
#define GOFF_BHH (GOFF_EPI + TB * LDEPI * 4)
#define GOFF_BIH (GOFF_BHH + H3 * 4)
#define GOFF_WIH (GOFF_BIH + H3 * 4)
#define SMEM_GRUTC (GOFF_WIH + H3 * 2 * 4)

template <int LAYER>
__global__ __launch_bounds__(512, 1) void gru_tc(
    const float* __restrict__ code,
    const float* __restrict__ xg,
    const float* __restrict__ Wih_f, const float* __restrict__ Wih_b,
    const float* __restrict__ Whh_f, const float* __restrict__ Whh_b,
    const float* __restrict__ bih_f, const float* __restrict__ bih_b,
    const float* __restrict__ bhh_f, const float* __restrict__ bhh_b,
    float* __restrict__ houtF,
    __nv_bfloat16* __restrict__ houtH,
    __nv_bfloat16* __restrict__ houtL)
{
    extern __shared__ char smem[];
    __nv_bfloat16* sWh = (__nv_bfloat16*)(smem + GOFF_WH);
    __nv_bfloat16* sWl = (__nv_bfloat16*)(smem + GOFF_WL);
    __nv_bfloat16* sHh = (__nv_bfloat16*)(smem + GOFF_HH);
    __nv_bfloat16* sHl = (__nv_bfloat16*)(smem + GOFF_HL);
    float* sEpi = (float*)(smem + GOFF_EPI);
    float* sBhh = (float*)(smem + GOFF_BHH);
    float* sBih = (float*)(smem + GOFF_BIH);
    float* sWih = (float*)(smem + GOFF_WIH);

    const int tid = threadIdx.x;
    const int dir = blockIdx.y;
    const int gb0 = blockIdx.x * TB;
    const float* Whh = dir ? Whh_b : Whh_f;
    const float* bhh = dir ? bhh_b : bhh_f;

    for (int idx = tid; idx < H3 * HID; idx += 512) {
        int r = idx >> 7, j = idx & 127;
        int g = r >> 7, k = r & 127;
        int colp = (k >> 6) * 192 + 3 * (k & 63) + g;
        float w = Whh[r * HID + j];
        __nv_bfloat16 hi = __float2bfloat16(w);
        __nv_bfloat16 lo = __float2bfloat16(w - __bfloat162float(hi));
        sWh[j * LDWP + colp] = hi;
        sWl[j * LDWP + colp] = lo;
    }
    for (int idx = tid; idx < H3; idx += 512) {
        sBhh[idx] = bhh[idx];
        if (LAYER == 0) {
            const float* Wih = dir ? Wih_b : Wih_f;
            const float* bih = dir ? bih_b : bih_f;
            sBih[idx] = bih[idx];
            sWih[idx * 2 + 0] = Wih[idx * 2 + 0];
            sWih[idx * 2 + 1] = Wih[idx * 2 + 1];
        }
    }
    for (int idx = tid; idx < TB * LDH; idx += 512) {
        sHh[idx] = __float2bfloat16(0.f);
        sHl[idx] = __float2bfloat16(0.f);
    }
    __syncthreads();

    const int wid = tid >> 5, lane = tid & 31;
    const int b = wid;
    const int k0 = lane * 2;
    float h[4] = {0.f, 0.f, 0.f, 0.f};

    for (int t = 0; t < SEQ; ++t) {
        const int tt = dir ? (SEQ - 1 - t) : t;

        float xr[4], xz[4], xn[4];
        if (LAYER == 1) {
            const float* xp = xg + ((size_t)dir * BL + (size_t)(gb0 + b) * SEQ + tt) * H3;
            float2 v;
            v = *(const float2*)(xp + k0);            xr[0] = v.x; xr[1] = v.y;
            v = *(const float2*)(xp + 64 + k0);       xr[2] = v.x; xr[3] = v.y;
            v = *(const float2*)(xp + 128 + k0);      xz[0] = v.x; xz[1] = v.y;
            v = *(const float2*)(xp + 192 + k0);      xz[2] = v.x; xz[3] = v.y;
            v = *(const float2*)(xp + 256 + k0);      xn[0] = v.x; xn[1] = v.y;
            v = *(const float2*)(xp + 320 + k0);      xn[2] = v.x; xn[3] = v.y;
        } else {
            float c0 = __ldg(&code[(size_t)(gb0 + b) * NLIN + tt * 2 + 0]);
            float c1 = __ldg(&code[(size_t)(gb0 + b) * NLIN + tt * 2 + 1]);
            #pragma unroll
            for (int i = 0; i < 4; ++i) {
                int k = (i >> 1) * 64 + k0 + (i & 1);
                xr[i] = fmaf(c0, sWih[k * 2],           fmaf(c1, sWih[k * 2 + 1],           sBih[k]));
                xz[i] = fmaf(c0, sWih[(128 + k) * 2],   fmaf(c1, sWih[(128 + k) * 2 + 1],   sBih[128 + k]));
                xn[i] = fmaf(c0, sWih[(256 + k) * 2],   fmaf(c1, sWih[(256 + k) * 2 + 1],   sBih[256 + k]));
            }
        }

        wmma::fragment<wmma::matrix_a, 16, 16, 16, __nv_bfloat16, wmma::row_major> aH[8], aL[8];
        if (wid < 12) {
            wmma::fragment<wmma::accumulator, 16, 16, 16, float> acc;
            wmma::fill_fragment(acc, 0.f);
            #pragma unroll
            for (int jf = 0; jf < 8; ++jf) {
                wmma::fragment<wmma::matrix_b, 16, 16, 16, __nv_bfloat16, wmma::row_major> bH, bL;
                wmma::load_matrix_sync(aH[jf], sHh + jf * 16, LDH);
                wmma::load_matrix_sync(aL[jf], sHl + jf * 16, LDH);
                wmma::load_matrix_sync(bH, sWh + (jf * 16) * LDWP + wid * 16, LDWP);
                wmma::load_matrix_sync(bL, sWl + (jf * 16) * LDWP + wid * 16, LDWP);
                wmma::mma_sync(acc, aH[jf], bH, acc);
                wmma::mma_sync(acc, aH[jf], bL, acc);
                wmma::mma_sync(acc, aL[jf], bH, acc);
            }
            wmma::store_matrix_sync(sEpi + wid * 16, acc, LDEPI, wmma::mem_row_major);
        }
        __syncthreads();

        #pragma unroll
        for (int i = 0; i < 2; ++i) {
            int k = k0 + i;
            const float* e = sEpi + b * LDEPI + 3 * k;
            float r = sigf(xr[i] + e[0] + sBhh[k]);
            float z = sigf(xz[i] + e[1] + sBhh[128 + k]);
            float n = tanhfast(xn[i] + r * (e[2] + sBhh[256 + k]));
            h[i] = (1.f - z) * n + z * h[i];
        }
        __syncthreads();

        if (wid < 12) {
            wmma::fragment<wmma::accumulator, 16, 16, 16, float> acc;
            wmma::fill_fragment(acc, 0.f);
            #pragma unroll
            for (int jf = 0; jf < 8; ++jf) {
                wmma::fragment<wmma::matrix_b, 16, 16, 16, __nv_bfloat16, wmma::row_major> bH, bL;
                wmma::load_matrix_sync(bH, sWh + (jf * 16) * LDWP + 192 + wid * 16, LDWP);
                wmma::load_matrix_sync(bL, sWl + (jf * 16) * LDWP + 192 + wid * 16, LDWP);
                wmma::mma_sync(acc, aH[jf], bH, acc);
                wmma::mma_sync(acc, aH[jf], bL, acc);
                wmma::mma_sync(acc, aL[jf], bH, acc);
            }
            wmma::store_matrix_sync(sEpi + wid * 16, acc, LDEPI, wmma::mem_row_major);
        }
        __syncthreads();

        #pragma unroll
        for (int i = 0; i < 2; ++i) {
            int kk = k0 + i;
            int k = 64 + kk;
            const float* e = sEpi + b * LDEPI + 3 * kk;
            float r = sigf(xr[2 + i] + e[0] + sBhh[k]);
            float z = sigf(xz[2 + i] + e[1] + sBhh[128 + k]);
            float n = tanhfast(xn[2 + i] + r * (e[2] + sBhh[256 + k]));
            h[2 + i] = (1.f - z) * n + z * h[2 + i];
        }

        const size_t orow = ((size_t)(gb0 + b) * SEQ + tt) * H2 + dir * HID;
        #pragma unroll
        for (int i = 0; i < 4; ++i) {
            int k = (i >> 1) * 64 + k0 + (i & 1);
            float v = h[i];
            __nv_bfloat16 hi = __float2bfloat16(v);
            __nv_bfloat16 lo = __float2bfloat16(v - __bfloat162float(hi));
            sHh[b * LDH + k] = hi;
            sHl[b * LDH + k] = lo;
            if (LAYER == 0) {
                houtH[orow + k] = hi;
                houtL[orow + k] = lo;
            } else {
                houtF[orow + k] = v;
            }
        }
        __syncthreads();
    }
}

// ---------------- final head ----------------
__global__ __launch_bounds__(256) void final_kernel(
    const float* __restrict__ h1, const float* __restrict__ Wf,
    const float* __restrict__ bf, float* __restrict__ out)
{
    __shared__ float sW[H2];
    int tid = threadIdx.x;
    sW[tid] = Wf[tid];
    __syncthreads();
    int w = tid >> 5, l = tid & 31;
    size_t row = (size_t)blockIdx.x * 8 + w;
    const float* hr = h1 + row * H2;
    float s = 0.f;
    #pragma unroll
    for (int i = 0; i < 8; ++i)
        s = fmaf(hr[l + i * 32], sW[l + i * 32], s);
    #pragma unroll
    for (int off = 16; off; off >>= 1)
        s += __shfl_xor_sync(0xffffffffu, s, off);
    if (l == 0)
        out[row] = 1.f / (1.f + __expf(-(s + bf[0])));
}

// ---------------- launch ----------------
extern "C" void kernel_launch(void* const* d_in, const int* in_sizes, int n_in,
                              void* d_out, int out_size)
{
    const float* received = (const float*)d_in[0];
    const float* W_lin    = (const float*)d_in[1];
    const float* b_lin    = (const float*)d_in[2];
    const float* Wih0f = (const float*)d_in[3],  *Whh0f = (const float*)d_in[4];
    const float* bih0f = (const float*)d_in[5],  *bhh0f = (const float*)d_in[6];
    const float* Wih0b = (const float*)d_in[7],  *Whh0b = (const float*)d_in[8];
    const float* bih0b = (const float*)d_in[9],  *bhh0b = (const float*)d_in[10];
    const float* Wih1f = (const float*)d_in[11], *Whh1f = (const float*)d_in[12];
    const float* bih1f = (const float*)d_in[13], *bhh1f = (const float*)d_in[14];
    const float* Wih1b = (const float*)d_in[15], *Whh1b = (const float*)d_in[16];
    const float* bih1b = (const float*)d_in[17], *bhh1b = (const float*)d_in[18];
    const float* Wf    = (const float*)d_in[19], *bf    = (const float*)d_in[20];
    float* out = (float*)d_out;

    float *code, *xg1, *h1;
    __nv_bfloat16 *ah, *al;
    cudaGetSymbolAddress((void**)&code, g_code);
    cudaGetSymbolAddress((void**)&ah,   g_ah);
    cudaGetSymbolAddress((void**)&al,   g_al);
    cudaGetSymbolAddress((void**)&xg1,  g_xg1);
    cudaGetSymbolAddress((void**)&h1,   g_h1);

    cudaFuncSetAttribute(gru_tc<0>, cudaFuncAttributeMaxDynamicSharedMemorySize, (int)SMEM_GRUTC);
    cudaFuncSetAttribute(gru_tc<1>, cudaFuncAttributeMaxDynamicSharedMemorySize, (int)SMEM_GRUTC);
    cudaFuncSetAttribute(xgemm3, cudaFuncAttributeMaxDynamicSharedMemorySize, (int)SMEM_X3);

    // 1) dec_linear
    sgemm_nt<<<dim3(BATCH / 64, (NLIN + 63) / 64), 256>>>(
        received, W_lin, b_lin, code, BATCH, NLIN, NLIN);

    // 2) layer-0 bidirectional GRU (R8-proven TC recurrence) -> bf16 hi/lo h0
    gru_tc<0><<<dim3(BATCH / TB, 2), 512, SMEM_GRUTC>>>(
        code, nullptr, Wih0f, Wih0b, Whh0f, Whh0b, bih0f, bih0b, bhh0f, bhh0b,
        nullptr, ah, al);

    // 3) layer-1 input projections (wmma bf16 v3: double-buffered, direct store)
    xgemm3<<<dim3(6, 200), 256, SMEM_X3>>>(
        ah, al, Wih1f, Wih1b, bih1f, bih1b, xg1);

    // 4) layer-1 bidirectional GRU
    gru_tc<1><<<dim3(BATCH / TB, 2), 512, SMEM_GRUTC>>>(
        nullptr, xg1, nullptr, nullptr, Whh1f, Whh1b, bih1f, bih1b, bhh1f, bhh1b,
        h1, nullptr, nullptr);

    // 5) output head
    final_kernel<<<BL / 8, 256>>>(h1, Wf, bf, out);
}